// round 13
// baseline (speedup 1.0000x reference)
#include <cuda_runtime.h>
#include <cuda_bf16.h>
#include <math.h>
#include <stdint.h>

#define BB 8
#define NN 2048
#define DD 128
#define KCAT 384
#define CSHIFT 80.0f
#define LOG2E 1.4426950408889634f

// ---------------- scratch (static device globals; no allocation) ----------
__device__ __nv_bfloat16 g_X1cat[(size_t)BB*NN*KCAT];  // A-role [hi|hi|lo]
__device__ __nv_bfloat16 g_X2cat[(size_t)BB*NN*KCAT];
__device__ __nv_bfloat16 g_Wkcat[DD*KCAT];             // B-role [hi|lo|hi]
__device__ __nv_bfloat16 g_Wvcat[DD*KCAT];
__device__ __nv_bfloat16 g_Wocat[DD*KCAT];
__device__ __nv_bfloat16 g_H1cat[(size_t)BB*NN*KCAT];  // [hi|hi|lo]
__device__ __nv_bfloat16 g_H2cat[(size_t)BB*NN*KCAT];  // [hi|lo|hi]
__device__ float g_V1[BB*NN*DD];
__device__ float g_V2[BB*NN*DD];
__device__ __nv_bfloat16 g_Eh[(size_t)BB*NN*NN];       // bf16(exp(S-C)), 67MB
__device__ float g_rowp[(size_t)BB*16*NN], g_colp[(size_t)BB*16*NN];
__device__ __nv_bfloat16 g_Vt1h[(size_t)BB*DD*NN], g_Vt1l[(size_t)BB*DD*NN];
__device__ __nv_bfloat16 g_Vt2h[(size_t)BB*DD*NN], g_Vt2l[(size_t)BB*DD*NN];
__device__ __nv_bfloat16 g_N12c[(size_t)BB*NN*KCAT];   // A-role cat
__device__ __nv_bfloat16 g_N21c[(size_t)BB*NN*KCAT];

// ---------------- mma.sync / ldmatrix / cp.async helpers -------------------
__device__ __forceinline__ void mma16816(float* d, const uint32_t* a, const uint32_t* b){
    asm volatile(
        "mma.sync.aligned.m16n8k16.row.col.f32.bf16.bf16.f32 "
        "{%0,%1,%2,%3},{%4,%5,%6,%7},{%8,%9},{%0,%1,%2,%3};\n"
        : "+f"(d[0]),"+f"(d[1]),"+f"(d[2]),"+f"(d[3])
        : "r"(a[0]),"r"(a[1]),"r"(a[2]),"r"(a[3]),"r"(b[0]),"r"(b[1]));
}
__device__ __forceinline__ void ldsm4(uint32_t* r, uint32_t addr){
    asm volatile("ldmatrix.sync.aligned.m8n8.x4.shared.b16 {%0,%1,%2,%3},[%4];\n"
        :"=r"(r[0]),"=r"(r[1]),"=r"(r[2]),"=r"(r[3]):"r"(addr));
}
__device__ __forceinline__ void ldsm4t(uint32_t* r, uint32_t addr){
    asm volatile("ldmatrix.sync.aligned.m8n8.x4.trans.shared.b16 {%0,%1,%2,%3},[%4];\n"
        :"=r"(r[0]),"=r"(r[1]),"=r"(r[2]),"=r"(r[3]):"r"(addr));
}
__device__ __forceinline__ uint32_t cvta_s(const void* p){
    return (uint32_t)__cvta_generic_to_shared(p);
}
__device__ __forceinline__ void cpa16(uint32_t dst, const void* src){
    asm volatile("cp.async.cg.shared.global [%0], [%1], 16;\n"::"r"(dst),"l"(src));
}
__device__ __forceinline__ void cp_commit(){ asm volatile("cp.async.commit_group;\n"); }
template<int N> __device__ __forceinline__ void cp_wait(){
    asm volatile("cp.async.wait_group %0;\n"::"n"(N));
}
__device__ __forceinline__ void split2(float a, float b,
                                       __nv_bfloat162& hp, __nv_bfloat162& lp){
    __nv_bfloat16 ha=__float2bfloat16(a), hb=__float2bfloat16(b);
    hp.x=ha; hp.y=hb;
    lp.x=__float2bfloat16(a-__bfloat162float(ha));
    lp.y=__float2bfloat16(b-__bfloat162float(hb));
}

#define STA 40
#define AVB 5120          // 128*STA elems per tile buffer

// ---------------- prep: fp32 -> cat layouts --------------------------------
__global__ __launch_bounds__(256,1) void xcat(
    const float* __restrict__ X1, const float* __restrict__ X2,
    __nv_bfloat16* __restrict__ C1, __nv_bfloat16* __restrict__ C2)
{
    int which = blockIdx.z;
    const float* X = which ? X2 : X1;
    __nv_bfloat16* C = which ? C2 : C1;
    size_t t = (size_t)blockIdx.x*256 + threadIdx.x;
    size_t r = t >> 5;
    int c4 = (int)(t & 31) * 4;
    float4 v = *(const float4*)(X + r*DD + c4);
    __nv_bfloat162 hp0,lp0,hp1,lp1;
    split2(v.x, v.y, hp0, lp0);
    split2(v.z, v.w, hp1, lp1);
    __nv_bfloat16* base = C + r*KCAT + c4;
    *(__nv_bfloat162*)(base)       = hp0; *(__nv_bfloat162*)(base+2)     = hp1;
    *(__nv_bfloat162*)(base+128)   = hp0; *(__nv_bfloat162*)(base+130)   = hp1;
    *(__nv_bfloat162*)(base+256)   = lp0; *(__nv_bfloat162*)(base+258)   = lp1;
}

__global__ __launch_bounds__(256,1) void wcat(
    const float* __restrict__ Wk, const float* __restrict__ Wv,
    const float* __restrict__ Wo,
    __nv_bfloat16* __restrict__ Ck, __nv_bfloat16* __restrict__ Cv,
    __nv_bfloat16* __restrict__ Co)
{
    int which = blockIdx.z;
    const float* W = (which==0) ? Wk : (which==1) ? Wv : Wo;
    __nv_bfloat16* C = (which==0) ? Ck : (which==1) ? Cv : Co;
    int t = blockIdx.x*256 + threadIdx.x;
    int r = t >> 5;
    int c4 = (t & 31) * 4;
    float4 v = *(const float4*)(W + r*DD + c4);
    __nv_bfloat162 hp0,lp0,hp1,lp1;
    split2(v.x, v.y, hp0, lp0);
    split2(v.z, v.w, hp1, lp1);
    __nv_bfloat16* base = C + r*KCAT + c4;
    *(__nv_bfloat162*)(base)       = hp0; *(__nv_bfloat162*)(base+2)     = hp1;
    *(__nv_bfloat162*)(base+128)   = lp0; *(__nv_bfloat162*)(base+130)   = lp1;
    *(__nv_bfloat162*)(base+256)   = hp0; *(__nv_bfloat162*)(base+258)   = hp1;
}

// ---------------- AV-style cat GEMM mainloop (shared by S / mma_cat) -------
// A tile 128x32 from Acat (stride KCAT), B tile 128x32 from Bcat (stride KCAT)
// warp tile 32x64, acc[2][8][4], 12 iterations, 2-stage cp.async.
#define CAT_MAINLOOP(Ab, Bb)                                                     \
    int ar = tid>>1, apart = tid&1;                                              \
    _Pragma("unroll 1")                                                          \
    for (int it=-1; it<12; it++) {                                               \
        int nx = it+1;                                                           \
        if (nx < 12) {                                                           \
            int st = nx & 1;                                                     \
            int p0 = nx*32;                                                      \
            uint32_t stB = base0 + (uint32_t)(st*2*AVB*2);                       \
            const __nv_bfloat16* ga = (Ab) + (size_t)ar*KCAT + p0 + apart*16;    \
            uint32_t sa = stB + (uint32_t)((ar*STA + apart*16)*2);               \
            cpa16(sa, ga); cpa16(sa+16, ga+8);                                   \
            const __nv_bfloat16* gb = (Bb) + (size_t)ar*KCAT + p0 + apart*16;    \
            uint32_t sb = stB + (uint32_t)(AVB*2) + (uint32_t)((ar*STA + apart*16)*2); \
            cpa16(sb, gb); cpa16(sb+16, gb+8);                                   \
            cp_commit();                                                         \
        }                                                                        \
        if (it < 0) continue;                                                    \
        if (nx < 12) cp_wait<1>(); else cp_wait<0>();                            \
        __syncthreads();                                                         \
        int st = it & 1;                                                         \
        uint32_t stB = base0 + (uint32_t)(st*2*AVB*2);                           \
        uint32_t aB  = stB;                                                      \
        uint32_t bB  = stB + (uint32_t)(AVB*2);                                  \
        _Pragma("unroll")                                                        \
        for (int ks=0; ks<2; ks++) {                                             \
            int kk = ks*16;                                                      \
            uint32_t af[2][4], bf[4][4];                                         \
            _Pragma("unroll")                                                    \
            for (int mi=0;mi<2;mi++)                                             \
                ldsm4(af[mi], aB + (uint32_t)(((wr+mi*16+lrow)*STA + kk + lcol)*2)); \
            _Pragma("unroll")                                                    \
            for (int nj=0;nj<4;nj++)                                             \
                ldsm4(bf[nj], bB + (uint32_t)(((wc+nj*16+lrow)*STA + kk + lcol)*2)); \
            _Pragma("unroll")                                                    \
            for (int mi=0;mi<2;mi++)                                             \
                _Pragma("unroll")                                                \
                for (int ni=0;ni<8;ni++) {                                       \
                    uint32_t bb[2] = { bf[ni>>1][ni&1], bf[ni>>1][(ni&1)+2] };   \
                    mma16816(acc[mi][ni], af[mi], bb);                           \
                }                                                                \
        }                                                                        \
        __syncthreads();                                                         \
    }

// ---------------- generic bf16-cat TN GEMM (K=384, N=128) ------------------
// EPI 0: fp32 store; 1: +bias, leaky; 2: H-cat split store
template<int EPI>
__global__ __launch_bounds__(256,1) void mma_cat(
    const __nv_bfloat16* __restrict__ A0, const __nv_bfloat16* __restrict__ A1,
    const __nv_bfloat16* __restrict__ Bcat,
    __nv_bfloat16* __restrict__ H0, __nv_bfloat16* __restrict__ H1,
    float* __restrict__ F0, float* __restrict__ F1,
    const float* __restrict__ bias)
{
    extern __shared__ __align__(16) char dyn_c[];
    int which = blockIdx.z, bx = blockIdx.x;
    const __nv_bfloat16* Ab = (which ? A1 : A0) + (size_t)bx*128*KCAT;
    int tid = threadIdx.x, lane = tid & 31, w = tid >> 5;
    int wr = (w&3)*32, wc = (w>>2)*64;
    uint32_t base0 = cvta_s(dyn_c);
    int lrow = lane & 15, lcol = (lane>>4)*8;
    float acc[2][8][4];
#pragma unroll
    for (int i=0;i<2;i++)
#pragma unroll
        for (int j=0;j<8;j++)
#pragma unroll
            for (int r=0;r<4;r++) acc[i][j][r]=0.f;

    CAT_MAINLOOP(Ab, Bcat)

    int g = lane>>2, tg = lane&3;
#pragma unroll
    for (int mi=0;mi<2;mi++) {
#pragma unroll
        for (int ni=0;ni<8;ni++) {
            int r0 = wr + mi*16 + g, c = wc + ni*8 + 2*tg;
            float e0=acc[mi][ni][0], e1=acc[mi][ni][1];
            float e2=acc[mi][ni][2], e3=acc[mi][ni][3];
            if (EPI==2) {
                __nv_bfloat16* Cb = (which ? H1 : H0) + (size_t)bx*128*KCAT;
                __nv_bfloat162 hp, lp;
                split2(e0, e1, hp, lp);
                __nv_bfloat16* p = Cb + (size_t)r0*KCAT + c;
                *(__nv_bfloat162*)(p)     = hp;
                *(__nv_bfloat162*)(p+128) = which ? lp : hp;
                *(__nv_bfloat162*)(p+256) = which ? hp : lp;
                split2(e2, e3, hp, lp);
                p = Cb + (size_t)(r0+8)*KCAT + c;
                *(__nv_bfloat162*)(p)     = hp;
                *(__nv_bfloat162*)(p+128) = which ? lp : hp;
                *(__nv_bfloat162*)(p+256) = which ? hp : lp;
            } else {
                float* Cb = (which ? F1 : F0) + (size_t)bx*128*DD;
                if (EPI==1) {
                    float b0 = bias[c], b1 = bias[c+1];
                    e0 += b0; e1 += b1; e2 += b0; e3 += b1;
                    e0 = e0>0.f? e0 : 0.01f*e0;
                    e1 = e1>0.f? e1 : 0.01f*e1;
                    e2 = e2>0.f? e2 : 0.01f*e2;
                    e3 = e3>0.f? e3 : 0.01f*e3;
                }
                *(float2*)(Cb + (size_t)r0*DD + c)     = make_float2(e0, e1);
                *(float2*)(Cb + (size_t)(r0+8)*DD + c) = make_float2(e2, e3);
            }
        }
    }
}

// ---------------- E = bf16(exp(S - C)) + self-normalized stats -------------
#define EPAD 136
__global__ __launch_bounds__(256,1) void gemm_s_exp(
    const __nv_bfloat16* __restrict__ Acat,
    const __nv_bfloat16* __restrict__ Bcat,
    __nv_bfloat16* __restrict__ Eh,
    float* __restrict__ rowp, float* __restrict__ colp)
{
    extern __shared__ __align__(16) char dyn_c[];
    __shared__ float rowsum[128], colsum[128];
    int b = blockIdx.z, bx = blockIdx.x, by = blockIdx.y;
    const __nv_bfloat16* Ab = Acat + (size_t)b*NN*KCAT + (size_t)bx*128*KCAT;
    const __nv_bfloat16* Bb = Bcat + (size_t)b*NN*KCAT + (size_t)by*128*KCAT;
    __nv_bfloat16* Ehb = Eh + (size_t)b*NN*NN + (size_t)bx*128*NN + by*128;
    int tid = threadIdx.x, lane = tid & 31, w = tid >> 5;
    int wr = (w&3)*32, wc = (w>>2)*64;
    uint32_t base0 = cvta_s(dyn_c);
    int lrow = lane & 15, lcol = (lane>>4)*8;
    float acc[2][8][4];
#pragma unroll
    for (int i=0;i<2;i++)
#pragma unroll
        for (int j=0;j<8;j++)
#pragma unroll
            for (int r=0;r<4;r++) acc[i][j][r]=0.f;
    if (tid < 128) { rowsum[tid]=0.f; colsum[tid]=0.f; }

    CAT_MAINLOOP(Ab, Bb)

    // ---- epilogue: exp, round, stage to smem (reuses pipeline buffers), stats
    __nv_bfloat16* SAB = (__nv_bfloat16*)dyn_c;   // 128*EPAD*2 = 34816 <= 40960
    int g = lane>>2, tg = lane&3;
    const float KEXP = -CSHIFT*LOG2E;
    float colA[8]={0,0,0,0,0,0,0,0}, colB[8]={0,0,0,0,0,0,0,0};
#pragma unroll
    for (int mi=0;mi<2;mi++) {
        int r0 = wr + mi*16 + g;
        float rs0 = 0.f, rs1 = 0.f;
#pragma unroll
        for (int ni=0;ni<8;ni++) {
            int c = wc + ni*8 + 2*tg;
            float e0 = exp2f(fmaf(acc[mi][ni][0], LOG2E, KEXP));
            float e1 = exp2f(fmaf(acc[mi][ni][1], LOG2E, KEXP));
            float e2 = exp2f(fmaf(acc[mi][ni][2], LOG2E, KEXP));
            float e3 = exp2f(fmaf(acc[mi][ni][3], LOG2E, KEXP));
            __nv_bfloat162 h01 = __floats2bfloat162_rn(e0, e1);
            __nv_bfloat162 h23 = __floats2bfloat162_rn(e2, e3);
            *(__nv_bfloat162*)(SAB + r0*EPAD + c)     = h01;
            *(__nv_bfloat162*)(SAB + (r0+8)*EPAD + c) = h23;
            float q0=__bfloat162float(h01.x), q1=__bfloat162float(h01.y);
            float q2=__bfloat162float(h23.x), q3=__bfloat162float(h23.y);
            rs0 += q0+q1; rs1 += q2+q3;
            colA[ni] += q0+q2; colB[ni] += q1+q3;
        }
        atomicAdd(&rowsum[r0],     rs0);
        atomicAdd(&rowsum[r0 + 8], rs1);
    }
#pragma unroll
    for (int ni=0;ni<8;ni++) {
        int c = wc + ni*8 + 2*tg;
        atomicAdd(&colsum[c],   colA[ni]);
        atomicAdd(&colsum[c+1], colB[ni]);
    }
    __syncthreads();
    {
        int row = tid >> 1, part = tid & 1;
        const int4* src4 = (const int4*)(SAB + row*EPAD + part*64);
        int4* d4 = (int4*)(Ehb + (size_t)row*NN + part*64);
#pragma unroll
        for (int q=0;q<8;q++) d4[q] = src4[q];
    }
    if (tid < 128) {
        rowp[((size_t)(b*16+by))*NN + bx*128 + tid] = rowsum[tid];
        colp[((size_t)(b*16+bx))*NN + by*128 + tid] = colsum[tid];
    }
}

// ---------------- V prep: fused Z-combine + scale + transpose + split ------
__global__ __launch_bounds__(256,1) void vprep(
    const float* __restrict__ V2, const float* __restrict__ colp,
    const float* __restrict__ V1, const float* __restrict__ rowp,
    __nv_bfloat16* __restrict__ Vt2h, __nv_bfloat16* __restrict__ Vt2l,
    __nv_bfloat16* __restrict__ Vt1h, __nv_bfloat16* __restrict__ Vt1l)
{
    __shared__ float sh[32][132];
    __shared__ float sc[32];
    int which = blockIdx.z >> 3, b = blockIdx.z & 7;
    const float* Vb = (which==0 ? V2 : V1) + (size_t)b*NN*DD;
    const float* pp = (which==0 ? colp : rowp);
    __nv_bfloat16* Vth = (which==0 ? Vt2h : Vt1h);
    __nv_bfloat16* Vtl = (which==0 ? Vt2l : Vt1l);
    int m0 = blockIdx.x*32;
    int tid = threadIdx.x;
    if (tid < 32) {
        float z = 0.f;
#pragma unroll
        for (int t=0;t<16;t++)
            z += pp[((size_t)(b*16+t))*NN + m0 + tid];
        sc[tid] = 1.f/z;
    }
    __syncthreads();
    {
        int r = tid>>3, c16 = (tid&7)*16;
        float s = sc[r];
        const float4* g = (const float4*)(Vb + (size_t)(m0+r)*DD + c16);
#pragma unroll
        for (int q=0;q<4;q++) {
            float4 v = g[q];
            v.x*=s; v.y*=s; v.z*=s; v.w*=s;
            *(float4*)&sh[r][c16+q*4] = v;
        }
    }
    __syncthreads();
    {
        int k = tid>>1, half = tid&1;
        union { __nv_bfloat16 bh[16]; int4 v4[2]; } uh, ul;
#pragma unroll
        for (int j=0;j<16;j++) {
            float f = sh[half*16+j][k];
            __nv_bfloat16 h = __float2bfloat16(f);
            uh.bh[j] = h;
            ul.bh[j] = __float2bfloat16(f - __bfloat162float(h));
        }
        __nv_bfloat16* oh = Vth + (size_t)b*DD*NN + (size_t)k*NN + m0 + half*16;
        __nv_bfloat16* ol = Vtl + (size_t)b*DD*NN + (size_t)k*NN + m0 + half*16;
        ((int4*)oh)[0]=uh.v4[0]; ((int4*)oh)[1]=uh.v4[1];
        ((int4*)ol)[0]=ul.v4[0]; ((int4*)ol)[1]=ul.v4[1];
    }
}

// ---------------- AV via mma.sync, pipelined, 2 passes, cat output ---------
#define STT 136
__global__ __launch_bounds__(256,1) void attn_av_bf16(
    const __nv_bfloat16* __restrict__ Eh,
    const __nv_bfloat16* __restrict__ Vt2h, const __nv_bfloat16* __restrict__ Vt2l,
    const __nv_bfloat16* __restrict__ Vt1h, const __nv_bfloat16* __restrict__ Vt1l,
    __nv_bfloat16* __restrict__ N12c, __nv_bfloat16* __restrict__ N21c)
{
    extern __shared__ __align__(16) char dyn_av[];
    int b = blockIdx.z, mode = blockIdx.y;
    const __nv_bfloat16* Ehb = Eh + (size_t)b*NN*NN;
    const __nv_bfloat16* Vhb = (mode==0 ? Vt2h : Vt1h) + (size_t)b*DD*NN;
    const __nv_bfloat16* Vlb = (mode==0 ? Vt2l : Vt1l) + (size_t)b*DD*NN;
    int rb = blockIdx.x*128;
    __nv_bfloat16* Ob = (mode==0 ? N12c : N21c) + (size_t)b*NN*KCAT + (size_t)rb*KCAT;
    int tid = threadIdx.x, lane = tid & 31, w = tid >> 5;
    int wr = (w&3)*32, wc = (w>>2)*64;
    uint32_t base0 = cvta_s(dyn_av);
    int lrow = lane & 15, lcol = (lane>>4)*8;
    int trow = (lane&7) + ((lane>>4)<<3);
    int tcol = ((lane>>3)&1)*8;
    float acc[2][8][4];
#pragma unroll
    for (int i=0;i<2;i++)
#pragma unroll
        for (int j=0;j<8;j++)
#pragma unroll
            for (int r=0;r<4;r++) acc[i][j][r]=0.f;

    int ar = tid>>1, apart = tid&1;
    int tr = tid>>3; int tcb = (tid&7)*16;

#pragma unroll 1
    for (int it=-1; it<64; it++) {
        int nx = it+1;
        if (nx < 64) {
            int st = nx & 1;
            int p0 = nx*32;
            uint32_t stB = base0 + (uint32_t)(st*3*AVB*2);
            if (mode==0) {
                const __nv_bfloat16* gh = Ehb + (size_t)(rb+ar)*NN + p0 + apart*16;
                uint32_t sa = stB + (uint32_t)((ar*STA + apart*16)*2);
                cpa16(sa, gh); cpa16(sa+16, gh+8);
            } else {
                const __nv_bfloat16* gh = Ehb + (size_t)(p0+tr)*NN + rb + tcb;
                uint32_t sa = stB + (uint32_t)((tr*STT + tcb)*2);
                cpa16(sa, gh); cpa16(sa+16, gh+8);
            }
            {
                const __nv_bfloat16* gh = Vhb + (size_t)ar*NN + p0 + apart*16;
                const __nv_bfloat16* gl = Vlb + (size_t)ar*NN + p0 + apart*16;
                uint32_t sb = stB + (uint32_t)(AVB*2) + (uint32_t)((ar*STA + apart*16)*2);
                cpa16(sb, gh); cpa16(sb+16, gh+8);
                uint32_t sl = sb + (uint32_t)(AVB*2);
                cpa16(sl, gl); cpa16(sl+16, gl+8);
            }
            cp_commit();
        }
        if (it < 0) continue;
        if (nx < 64) cp_wait<1>(); else cp_wait<0>();
        __syncthreads();
        int st = it & 1;
        uint32_t stB = base0 + (uint32_t)(st*3*AVB*2);
        uint32_t aB  = stB;
        uint32_t bB  = stB + (uint32_t)(AVB*2);
        uint32_t blB = stB + (uint32_t)(2*AVB*2);
#pragma unroll
        for (int pass=0; pass<2; pass++) {
            uint32_t bBase = (pass==0) ? bB : blB;
#pragma unroll
            for (int ks=0; ks<2; ks++) {
                int kk = ks*16;
                uint32_t af[2][4], bf[4][4];
#pragma unroll
                for (int mi=0;mi<2;mi++) {
                    if (mode==0)
                        ldsm4 (af[mi], aB + (uint32_t)(((wr+mi*16+lrow)*STA + kk + lcol)*2));
                    else
                        ldsm4t(af[mi], aB + (uint32_t)(((kk+trow)*STT + wr + mi*16 + tcol)*2));
                }
#pragma unroll
                for (int nj=0;nj<4;nj++)
                    ldsm4(bf[nj], bBase + (uint32_t)(((wc+nj*16+lrow)*STA + kk + lcol)*2));
#pragma unroll
                for (int mi=0;mi<2;mi++)
#pragma unroll
                    for (int ni=0;ni<8;ni++) {
                        uint32_t bb[2] = { bf[ni>>1][ni&1], bf[ni>>1][(ni&1)+2] };
                        mma16816(acc[mi][ni], af[mi], bb);
                    }
            }
        }
        __syncthreads();
    }
    // epilogue: write A-role cat [hi|hi|lo]
    int g = lane>>2, tg = lane&3;
#pragma unroll
    for (int mi=0;mi<2;mi++)
#pragma unroll
        for (int ni=0;ni<8;ni++) {
            int r0 = wr + mi*16 + g, c = wc + ni*8 + 2*tg;
            __nv_bfloat162 hp, lp;
            split2(acc[mi][ni][0], acc[mi][ni][1], hp, lp);
            __nv_bfloat16* p = Ob + (size_t)r0*KCAT + c;
            *(__nv_bfloat162*)(p)     = hp;
            *(__nv_bfloat162*)(p+128) = hp;
            *(__nv_bfloat162*)(p+256) = lp;
            split2(acc[mi][ni][2], acc[mi][ni][3], hp, lp);
            p = Ob + (size_t)(r0+8)*KCAT + c;
            *(__nv_bfloat162*)(p)     = hp;
            *(__nv_bfloat162*)(p+128) = hp;
            *(__nv_bfloat162*)(p+256) = lp;
        }
}

// ---------------- launch ---------------------------------------------------
extern "C" void kernel_launch(void* const* d_in, const int* in_sizes, int n_in,
                              void* d_out, int out_size)
{
    const float* x1 = (const float*)d_in[0];
    const float* x2 = (const float*)d_in[1];
    const float* Wk = (const float*)d_in[2];
    const float* Wv = (const float*)d_in[3];
    const float* Wo = (const float*)d_in[4];
    const float* bo = (const float*)d_in[5];
    float* msg1 = (float*)d_out;
    float* msg2 = msg1 + (size_t)BB*NN*DD;

    __nv_bfloat16 *X1c,*X2c,*Wkc,*Wvc,*Woc,*H1c,*H2c,*Eh,*Vt1h,*Vt1l,*Vt2h,*Vt2l,*N12c,*N21c;
    float *V1,*V2,*rowp,*colp;
    cudaGetSymbolAddress((void**)&X1c, g_X1cat);
    cudaGetSymbolAddress((void**)&X2c, g_X2cat);
    cudaGetSymbolAddress((void**)&Wkc, g_Wkcat);
    cudaGetSymbolAddress((void**)&Wvc, g_Wvcat);
    cudaGetSymbolAddress((void**)&Woc, g_Wocat);
    cudaGetSymbolAddress((void**)&H1c, g_H1cat);
    cudaGetSymbolAddress((void**)&H2c, g_H2cat);
    cudaGetSymbolAddress((void**)&V1,  g_V1);
    cudaGetSymbolAddress((void**)&V2,  g_V2);
    cudaGetSymbolAddress((void**)&Eh,  g_Eh);
    cudaGetSymbolAddress((void**)&rowp,g_rowp);
    cudaGetSymbolAddress((void**)&colp,g_colp);
    cudaGetSymbolAddress((void**)&Vt1h,g_Vt1h);
    cudaGetSymbolAddress((void**)&Vt1l,g_Vt1l);
    cudaGetSymbolAddress((void**)&Vt2h,g_Vt2h);
    cudaGetSymbolAddress((void**)&Vt2l,g_Vt2l);
    cudaGetSymbolAddress((void**)&N12c,g_N12c);
    cudaGetSymbolAddress((void**)&N21c,g_N21c);

    const int CAT_DYN = 2*2*AVB*2;             // 40960 B (pipeline / epi staging)
    const int AV_DYN  = 2*3*AVB*2;             // 61440 B
    static bool attr_done = false;
    if (!attr_done) {
        cudaFuncSetAttribute(mma_cat<0>,  cudaFuncAttributeMaxDynamicSharedMemorySize, CAT_DYN);
        cudaFuncSetAttribute(mma_cat<1>,  cudaFuncAttributeMaxDynamicSharedMemorySize, CAT_DYN);
        cudaFuncSetAttribute(mma_cat<2>,  cudaFuncAttributeMaxDynamicSharedMemorySize, CAT_DYN);
        cudaFuncSetAttribute(gemm_s_exp,  cudaFuncAttributeMaxDynamicSharedMemorySize, CAT_DYN);
        cudaFuncSetAttribute(attn_av_bf16,cudaFuncAttributeMaxDynamicSharedMemorySize, AV_DYN);
        attr_done = true;
    }

    dim3 thr(256);

    // 0) split inputs/weights to cat layouts
    xcat<<<dim3(2048,1,2),thr>>>(x1, x2, X1c, X2c);
    wcat<<<dim3(16,1,3),thr>>>(Wk, Wv, Wo, Wkc, Wvc, Woc);

    // 1) projections via mma: K -> H cat, V -> fp32
    mma_cat<2><<<dim3(128,1,2),thr,CAT_DYN>>>(X1c, X2c, Wkc, H1c, H2c, nullptr, nullptr, nullptr);
    mma_cat<0><<<dim3(128,1,2),thr,CAT_DYN>>>(X1c, X2c, Wvc, nullptr, nullptr, V1, V2, nullptr);

    // 2) E = bf16(exp(S - C)) + self-normalized stats
    gemm_s_exp<<<dim3(16,16,8),thr,CAT_DYN>>>(H1c, H2c, Eh, rowp, colp);

    // 3) V: fused Z-combine + scale + transpose + split
    vprep<<<dim3(64,1,16),thr>>>(V2, colp, V1, rowp, Vt2h, Vt2l, Vt1h, Vt1l);

    // 4) AV (writes N cat directly)
    attn_av_bf16<<<dim3(16,2,8),thr,AV_DYN>>>(Eh, Vt2h, Vt2l, Vt1h, Vt1l, N12c, N21c);

    // 5) output projection + bias + leaky relu via mma
    mma_cat<1><<<dim3(128,1,2),thr,CAT_DYN>>>(N12c, N21c, Woc, nullptr, nullptr, msg1, msg2, bo);
}

// round 14
// speedup vs baseline: 1.0604x; 1.0604x over previous
#include <cuda_runtime.h>
#include <cuda_bf16.h>
#include <math.h>
#include <stdint.h>

#define BB 8
#define NN 2048
#define DD 128
#define KCAT 384
#define CSHIFT 80.0f
#define LOG2E 1.4426950408889634f

// ---------------- scratch (static device globals; no allocation) ----------
__device__ __nv_bfloat16 g_X1cat[(size_t)BB*NN*KCAT];  // A-role [hi|hi|lo]
__device__ __nv_bfloat16 g_X2cat[(size_t)BB*NN*KCAT];
__device__ __nv_bfloat16 g_Wkcat[DD*KCAT];             // B-role [hi|lo|hi]
__device__ __nv_bfloat16 g_Wvcat[DD*KCAT];
__device__ __nv_bfloat16 g_Wocat[DD*KCAT];
__device__ __nv_bfloat16 g_H1cat[(size_t)BB*NN*KCAT];  // [hi|hi|lo]
__device__ __nv_bfloat16 g_H2cat[(size_t)BB*NN*KCAT];  // [hi|lo|hi]
__device__ float g_V1[BB*NN*DD];
__device__ float g_V2[BB*NN*DD];
__device__ __nv_bfloat16 g_Eh[(size_t)BB*NN*NN];       // bf16(exp(S-C)), 67MB
__device__ float g_rowp[(size_t)BB*16*NN], g_colp[(size_t)BB*16*NN];
__device__ __nv_bfloat16 g_Vt1h[(size_t)BB*DD*NN], g_Vt1l[(size_t)BB*DD*NN];
__device__ __nv_bfloat16 g_Vt2h[(size_t)BB*DD*NN], g_Vt2l[(size_t)BB*DD*NN];
__device__ __nv_bfloat16 g_N12c[(size_t)BB*NN*KCAT];   // A-role cat
__device__ __nv_bfloat16 g_N21c[(size_t)BB*NN*KCAT];

// ---------------- mma.sync / ldmatrix / cp.async helpers -------------------
__device__ __forceinline__ void mma16816(float* d, const uint32_t* a, const uint32_t* b){
    asm volatile(
        "mma.sync.aligned.m16n8k16.row.col.f32.bf16.bf16.f32 "
        "{%0,%1,%2,%3},{%4,%5,%6,%7},{%8,%9},{%0,%1,%2,%3};\n"
        : "+f"(d[0]),"+f"(d[1]),"+f"(d[2]),"+f"(d[3])
        : "r"(a[0]),"r"(a[1]),"r"(a[2]),"r"(a[3]),"r"(b[0]),"r"(b[1]));
}
__device__ __forceinline__ void ldsm4(uint32_t* r, uint32_t addr){
    asm volatile("ldmatrix.sync.aligned.m8n8.x4.shared.b16 {%0,%1,%2,%3},[%4];\n"
        :"=r"(r[0]),"=r"(r[1]),"=r"(r[2]),"=r"(r[3]):"r"(addr));
}
__device__ __forceinline__ void ldsm4t(uint32_t* r, uint32_t addr){
    asm volatile("ldmatrix.sync.aligned.m8n8.x4.trans.shared.b16 {%0,%1,%2,%3},[%4];\n"
        :"=r"(r[0]),"=r"(r[1]),"=r"(r[2]),"=r"(r[3]):"r"(addr));
}
__device__ __forceinline__ uint32_t cvta_s(const void* p){
    return (uint32_t)__cvta_generic_to_shared(p);
}
__device__ __forceinline__ void cpa16(uint32_t dst, const void* src){
    asm volatile("cp.async.cg.shared.global [%0], [%1], 16;\n"::"r"(dst),"l"(src));
}
__device__ __forceinline__ void cp_commit(){ asm volatile("cp.async.commit_group;\n"); }
template<int N> __device__ __forceinline__ void cp_wait(){
    asm volatile("cp.async.wait_group %0;\n"::"n"(N));
}
__device__ __forceinline__ void split2(float a, float b,
                                       __nv_bfloat162& hp, __nv_bfloat162& lp){
    __nv_bfloat16 ha=__float2bfloat16(a), hb=__float2bfloat16(b);
    hp.x=ha; hp.y=hb;
    lp.x=__float2bfloat16(a-__bfloat162float(ha));
    lp.y=__float2bfloat16(b-__bfloat162float(hb));
}

// ---------------- prep: fp32 -> cat layouts --------------------------------
__global__ __launch_bounds__(256,1) void xcat(
    const float* __restrict__ X1, const float* __restrict__ X2,
    __nv_bfloat16* __restrict__ C1, __nv_bfloat16* __restrict__ C2)
{
    int which = blockIdx.z;
    const float* X = which ? X2 : X1;
    __nv_bfloat16* C = which ? C2 : C1;
    size_t t = (size_t)blockIdx.x*256 + threadIdx.x;
    size_t r = t >> 5;
    int c4 = (int)(t & 31) * 4;
    float4 v = *(const float4*)(X + r*DD + c4);
    __nv_bfloat162 hp0,lp0,hp1,lp1;
    split2(v.x, v.y, hp0, lp0);
    split2(v.z, v.w, hp1, lp1);
    __nv_bfloat16* base = C + r*KCAT + c4;
    *(__nv_bfloat162*)(base)       = hp0; *(__nv_bfloat162*)(base+2)     = hp1;
    *(__nv_bfloat162*)(base+128)   = hp0; *(__nv_bfloat162*)(base+130)   = hp1;
    *(__nv_bfloat162*)(base+256)   = lp0; *(__nv_bfloat162*)(base+258)   = lp1;
}

__global__ __launch_bounds__(256,1) void wcat(
    const float* __restrict__ Wk, const float* __restrict__ Wv,
    const float* __restrict__ Wo,
    __nv_bfloat16* __restrict__ Ck, __nv_bfloat16* __restrict__ Cv,
    __nv_bfloat16* __restrict__ Co)
{
    int which = blockIdx.z;
    const float* W = (which==0) ? Wk : (which==1) ? Wv : Wo;
    __nv_bfloat16* C = (which==0) ? Ck : (which==1) ? Cv : Co;
    int t = blockIdx.x*256 + threadIdx.x;
    int r = t >> 5;
    int c4 = (t & 31) * 4;
    float4 v = *(const float4*)(W + r*DD + c4);
    __nv_bfloat162 hp0,lp0,hp1,lp1;
    split2(v.x, v.y, hp0, lp0);
    split2(v.z, v.w, hp1, lp1);
    __nv_bfloat16* base = C + r*KCAT + c4;
    *(__nv_bfloat162*)(base)       = hp0; *(__nv_bfloat162*)(base+2)     = hp1;
    *(__nv_bfloat162*)(base+128)   = lp0; *(__nv_bfloat162*)(base+130)   = lp1;
    *(__nv_bfloat162*)(base+256)   = hp0; *(__nv_bfloat162*)(base+258)   = hp1;
}

// ---------------- R12-style cat mainloop (STS=72, 6 x K64 iters) -----------
#define STS 72

#define CAT12_MAINLOOP(Ab, Bb)                                                   \
    int row = tid >> 1, part = tid & 1;                                          \
    for (int k0=0;k0<KCAT;k0+=64) {                                              \
        const int4* ga = (const int4*)((Ab) + (size_t)row*KCAT + k0 + part*32);  \
        const int4* gb = (const int4*)((Bb) + (size_t)row*KCAT + k0 + part*32);  \
        int4* sa = (int4*)(As + row*STS + part*32);                              \
        int4* sb = (int4*)(Bs + row*STS + part*32);                              \
        sa[0]=ga[0]; sa[1]=ga[1]; sa[2]=ga[2]; sa[3]=ga[3];                      \
        sb[0]=gb[0]; sb[1]=gb[1]; sb[2]=gb[2]; sb[3]=gb[3];                      \
        __syncthreads();                                                         \
        _Pragma("unroll")                                                        \
        for (int ks=0; ks<4; ks++) {                                             \
            int kk = ks*16;                                                      \
            uint32_t af[4][4], bf[2][4];                                         \
            _Pragma("unroll")                                                    \
            for (int mi=0;mi<4;mi++)                                             \
                ldsm4(af[mi], aB + (uint32_t)(((wr+mi*16+lrow)*STS + kk + lcol)*2)); \
            _Pragma("unroll")                                                    \
            for (int nj=0;nj<2;nj++)                                             \
                ldsm4(bf[nj], bB + (uint32_t)(((wc+nj*16+lrow)*STS + kk + lcol)*2)); \
            _Pragma("unroll")                                                    \
            for (int mi=0;mi<4;mi++)                                             \
                _Pragma("unroll")                                                \
                for (int ni=0;ni<4;ni++) {                                       \
                    uint32_t bb[2] = { bf[ni>>1][ni&1], bf[ni>>1][(ni&1)+2] };   \
                    mma16816(acc[mi][ni], af[mi], bb);                           \
                }                                                                \
        }                                                                        \
        __syncthreads();                                                         \
    }

// ---------------- merged K/V projection (one launch, z=4) ------------------
// z&1 = which input (x1/x2); z>>1 = proj (0: Wk -> H cat, 1: Wv -> V fp32)
__global__ __launch_bounds__(256,1) void mma_kv(
    const __nv_bfloat16* __restrict__ X1c, const __nv_bfloat16* __restrict__ X2c,
    const __nv_bfloat16* __restrict__ Wkc, const __nv_bfloat16* __restrict__ Wvc,
    __nv_bfloat16* __restrict__ H1c, __nv_bfloat16* __restrict__ H2c,
    float* __restrict__ V1, float* __restrict__ V2)
{
    __shared__ __align__(16) __nv_bfloat16 SAB[2*128*STS];
    __nv_bfloat16* As = SAB;
    __nv_bfloat16* Bs = SAB + 128*STS;
    int which = blockIdx.z & 1, proj = blockIdx.z >> 1, bx = blockIdx.x;
    const __nv_bfloat16* Ab = (which ? X2c : X1c) + (size_t)bx*128*KCAT;
    const __nv_bfloat16* Bcat = proj ? Wvc : Wkc;
    int tid = threadIdx.x, lane = tid & 31, w = tid >> 5;
    int wr = (w>>2)*64, wc = (w&3)*32;
    uint32_t aB = cvta_s(As), bB = cvta_s(Bs);
    int lrow = lane & 15, lcol = (lane>>4)*8;
    float acc[4][4][4];
#pragma unroll
    for (int i=0;i<4;i++)
#pragma unroll
        for (int j=0;j<4;j++)
#pragma unroll
            for (int r=0;r<4;r++) acc[i][j][r]=0.f;

    CAT12_MAINLOOP(Ab, Bcat)

    int g = lane>>2, tg = lane&3;
#pragma unroll
    for (int mi=0;mi<4;mi++) {
#pragma unroll
        for (int ni=0;ni<4;ni++) {
            int r0 = wr + mi*16 + g, c = wc + ni*8 + 2*tg;
            float e0=acc[mi][ni][0], e1=acc[mi][ni][1];
            float e2=acc[mi][ni][2], e3=acc[mi][ni][3];
            if (proj==0) {
                __nv_bfloat16* Cb = (which ? H2c : H1c) + (size_t)bx*128*KCAT;
                __nv_bfloat162 hp, lp;
                split2(e0, e1, hp, lp);
                __nv_bfloat16* p = Cb + (size_t)r0*KCAT + c;
                *(__nv_bfloat162*)(p)     = hp;
                *(__nv_bfloat162*)(p+128) = which ? lp : hp;
                *(__nv_bfloat162*)(p+256) = which ? hp : lp;
                split2(e2, e3, hp, lp);
                p = Cb + (size_t)(r0+8)*KCAT + c;
                *(__nv_bfloat162*)(p)     = hp;
                *(__nv_bfloat162*)(p+128) = which ? lp : hp;
                *(__nv_bfloat162*)(p+256) = which ? hp : lp;
            } else {
                float* Cb = (which ? V2 : V1) + (size_t)bx*128*DD;
                *(float2*)(Cb + (size_t)r0*DD + c)     = make_float2(e0, e1);
                *(float2*)(Cb + (size_t)(r0+8)*DD + c) = make_float2(e2, e3);
            }
        }
    }
}

// ---------------- output projection + bias + leaky (R12 style) -------------
__global__ __launch_bounds__(256,1) void mma_out(
    const __nv_bfloat16* __restrict__ A0, const __nv_bfloat16* __restrict__ A1,
    const __nv_bfloat16* __restrict__ Bcat,
    float* __restrict__ F0, float* __restrict__ F1,
    const float* __restrict__ bias)
{
    __shared__ __align__(16) __nv_bfloat16 SAB[2*128*STS];
    __nv_bfloat16* As = SAB;
    __nv_bfloat16* Bs = SAB + 128*STS;
    int which = blockIdx.z, bx = blockIdx.x;
    const __nv_bfloat16* Ab = (which ? A1 : A0) + (size_t)bx*128*KCAT;
    int tid = threadIdx.x, lane = tid & 31, w = tid >> 5;
    int wr = (w>>2)*64, wc = (w&3)*32;
    uint32_t aB = cvta_s(As), bB = cvta_s(Bs);
    int lrow = lane & 15, lcol = (lane>>4)*8;
    float acc[4][4][4];
#pragma unroll
    for (int i=0;i<4;i++)
#pragma unroll
        for (int j=0;j<4;j++)
#pragma unroll
            for (int r=0;r<4;r++) acc[i][j][r]=0.f;

    CAT12_MAINLOOP(Ab, Bcat)

    int g = lane>>2, tg = lane&3;
#pragma unroll
    for (int mi=0;mi<4;mi++) {
#pragma unroll
        for (int ni=0;ni<4;ni++) {
            int r0 = wr + mi*16 + g, c = wc + ni*8 + 2*tg;
            float e0=acc[mi][ni][0], e1=acc[mi][ni][1];
            float e2=acc[mi][ni][2], e3=acc[mi][ni][3];
            float b0 = bias[c], b1 = bias[c+1];
            e0 += b0; e1 += b1; e2 += b0; e3 += b1;
            e0 = e0>0.f? e0 : 0.01f*e0;
            e1 = e1>0.f? e1 : 0.01f*e1;
            e2 = e2>0.f? e2 : 0.01f*e2;
            e3 = e3>0.f? e3 : 0.01f*e3;
            float* Cb = (which ? F1 : F0) + (size_t)bx*128*DD;
            *(float2*)(Cb + (size_t)r0*DD + c)     = make_float2(e0, e1);
            *(float2*)(Cb + (size_t)(r0+8)*DD + c) = make_float2(e2, e3);
        }
    }
}

// ---------------- E = bf16(exp(S - C)) + self-normalized stats (R12) -------
#define EPAD 136
__global__ __launch_bounds__(256,1) void gemm_s_exp(
    const __nv_bfloat16* __restrict__ Acat,
    const __nv_bfloat16* __restrict__ Bcat,
    __nv_bfloat16* __restrict__ Eh,
    float* __restrict__ rowp, float* __restrict__ colp)
{
    __shared__ __align__(16) __nv_bfloat16 SAB[2*128*STS];
    __shared__ float rowsum[128], colsum[128];
    __nv_bfloat16* As = SAB;
    __nv_bfloat16* Bs = SAB + 128*STS;
    int b = blockIdx.z, bx = blockIdx.x, by = blockIdx.y;
    const __nv_bfloat16* Ab = Acat + (size_t)b*NN*KCAT + (size_t)bx*128*KCAT;
    const __nv_bfloat16* Bb = Bcat + (size_t)b*NN*KCAT + (size_t)by*128*KCAT;
    __nv_bfloat16* Ehb = Eh + (size_t)b*NN*NN + (size_t)bx*128*NN + by*128;
    int tid = threadIdx.x, lane = tid & 31, w = tid >> 5;
    int wr = (w>>2)*64, wc = (w&3)*32;
    uint32_t aB = cvta_s(As), bB = cvta_s(Bs);
    int lrow = lane & 15, lcol = (lane>>4)*8;
    float acc[4][4][4];
#pragma unroll
    for (int i=0;i<4;i++)
#pragma unroll
        for (int j=0;j<4;j++)
#pragma unroll
            for (int r=0;r<4;r++) acc[i][j][r]=0.f;
    if (tid < 128) { rowsum[tid]=0.f; colsum[tid]=0.f; }

    CAT12_MAINLOOP(Ab, Bb)

    int g = lane>>2, tg = lane&3;
    const float KEXP = -CSHIFT*LOG2E;
    float colA[4]={0,0,0,0}, colB[4]={0,0,0,0};
#pragma unroll
    for (int mi=0;mi<4;mi++) {
        int r0 = wr + mi*16 + g;
        float rs0 = 0.f, rs1 = 0.f;
#pragma unroll
        for (int ni=0;ni<4;ni++) {
            int c = wc + ni*8 + 2*tg;
            float e0 = exp2f(fmaf(acc[mi][ni][0], LOG2E, KEXP));
            float e1 = exp2f(fmaf(acc[mi][ni][1], LOG2E, KEXP));
            float e2 = exp2f(fmaf(acc[mi][ni][2], LOG2E, KEXP));
            float e3 = exp2f(fmaf(acc[mi][ni][3], LOG2E, KEXP));
            __nv_bfloat162 h01 = __floats2bfloat162_rn(e0, e1);
            __nv_bfloat162 h23 = __floats2bfloat162_rn(e2, e3);
            *(__nv_bfloat162*)(SAB + r0*EPAD + c)     = h01;
            *(__nv_bfloat162*)(SAB + (r0+8)*EPAD + c) = h23;
            float q0=__bfloat162float(h01.x), q1=__bfloat162float(h01.y);
            float q2=__bfloat162float(h23.x), q3=__bfloat162float(h23.y);
            rs0 += q0+q1; rs1 += q2+q3;
            colA[ni] += q0+q2; colB[ni] += q1+q3;
        }
        atomicAdd(&rowsum[r0],     rs0);
        atomicAdd(&rowsum[r0 + 8], rs1);
    }
#pragma unroll
    for (int ni=0;ni<4;ni++) {
        int c = wc + ni*8 + 2*tg;
        atomicAdd(&colsum[c],   colA[ni]);
        atomicAdd(&colsum[c+1], colB[ni]);
    }
    __syncthreads();
    {
        int row = tid >> 1, part = tid & 1;
        const int4* src4 = (const int4*)(SAB + row*EPAD + part*64);
        int4* d4 = (int4*)(Ehb + (size_t)row*NN + part*64);
#pragma unroll
        for (int q=0;q<8;q++) d4[q] = src4[q];
    }
    if (tid < 128) {
        rowp[((size_t)(b*16+by))*NN + bx*128 + tid] = rowsum[tid];
        colp[((size_t)(b*16+bx))*NN + by*128 + tid] = colsum[tid];
    }
}

// ---------------- V prep: fused Z-combine + scale + transpose + split ------
__global__ __launch_bounds__(256,1) void vprep(
    const float* __restrict__ V2, const float* __restrict__ colp,
    const float* __restrict__ V1, const float* __restrict__ rowp,
    __nv_bfloat16* __restrict__ Vt2h, __nv_bfloat16* __restrict__ Vt2l,
    __nv_bfloat16* __restrict__ Vt1h, __nv_bfloat16* __restrict__ Vt1l)
{
    __shared__ float sh[32][132];
    __shared__ float sc[32];
    int which = blockIdx.z >> 3, b = blockIdx.z & 7;
    const float* Vb = (which==0 ? V2 : V1) + (size_t)b*NN*DD;
    const float* pp = (which==0 ? colp : rowp);
    __nv_bfloat16* Vth = (which==0 ? Vt2h : Vt1h);
    __nv_bfloat16* Vtl = (which==0 ? Vt2l : Vt1l);
    int m0 = blockIdx.x*32;
    int tid = threadIdx.x;
    if (tid < 32) {
        float z = 0.f;
#pragma unroll
        for (int t=0;t<16;t++)
            z += pp[((size_t)(b*16+t))*NN + m0 + tid];
        sc[tid] = 1.f/z;
    }
    __syncthreads();
    {
        int r = tid>>3, c16 = (tid&7)*16;
        float s = sc[r];
        const float4* g = (const float4*)(Vb + (size_t)(m0+r)*DD + c16);
#pragma unroll
        for (int q=0;q<4;q++) {
            float4 v = g[q];
            v.x*=s; v.y*=s; v.z*=s; v.w*=s;
            *(float4*)&sh[r][c16+q*4] = v;
        }
    }
    __syncthreads();
    {
        int k = tid>>1, half = tid&1;
        union { __nv_bfloat16 bh[16]; int4 v4[2]; } uh, ul;
#pragma unroll
        for (int j=0;j<16;j++) {
            float f = sh[half*16+j][k];
            __nv_bfloat16 h = __float2bfloat16(f);
            uh.bh[j] = h;
            ul.bh[j] = __float2bfloat16(f - __bfloat162float(h));
        }
        __nv_bfloat16* oh = Vth + (size_t)b*DD*NN + (size_t)k*NN + m0 + half*16;
        __nv_bfloat16* ol = Vtl + (size_t)b*DD*NN + (size_t)k*NN + m0 + half*16;
        ((int4*)oh)[0]=uh.v4[0]; ((int4*)oh)[1]=uh.v4[1];
        ((int4*)ol)[0]=ul.v4[0]; ((int4*)ol)[1]=ul.v4[1];
    }
}

// ---------------- AV via mma.sync, pipelined, 2 passes, cat output ---------
#define STA 40
#define STT 136
#define AVBUF 5120
__global__ __launch_bounds__(256,1) void attn_av_bf16(
    const __nv_bfloat16* __restrict__ Eh,
    const __nv_bfloat16* __restrict__ Vt2h, const __nv_bfloat16* __restrict__ Vt2l,
    const __nv_bfloat16* __restrict__ Vt1h, const __nv_bfloat16* __restrict__ Vt1l,
    __nv_bfloat16* __restrict__ N12c, __nv_bfloat16* __restrict__ N21c)
{
    extern __shared__ __align__(16) char dyn_av[];
    int b = blockIdx.z, mode = blockIdx.y;
    const __nv_bfloat16* Ehb = Eh + (size_t)b*NN*NN;
    const __nv_bfloat16* Vhb = (mode==0 ? Vt2h : Vt1h) + (size_t)b*DD*NN;
    const __nv_bfloat16* Vlb = (mode==0 ? Vt2l : Vt1l) + (size_t)b*DD*NN;
    int rb = blockIdx.x*128;
    __nv_bfloat16* Ob = (mode==0 ? N12c : N21c) + (size_t)b*NN*KCAT + (size_t)rb*KCAT;
    int tid = threadIdx.x, lane = tid & 31, w = tid >> 5;
    int wr = (w&3)*32, wc = (w>>2)*64;
    uint32_t base0 = cvta_s(dyn_av);
    int lrow = lane & 15, lcol = (lane>>4)*8;
    int trow = (lane&7) + ((lane>>4)<<3);
    int tcol = ((lane>>3)&1)*8;
    float acc[2][8][4];
#pragma unroll
    for (int i=0;i<2;i++)
#pragma unroll
        for (int j=0;j<8;j++)
#pragma unroll
            for (int r=0;r<4;r++) acc[i][j][r]=0.f;

    int ar = tid>>1, apart = tid&1;
    int tr = tid>>3; int tcb = (tid&7)*16;

#pragma unroll 1
    for (int it=-1; it<64; it++) {
        int nx = it+1;
        if (nx < 64) {
            int st = nx & 1;
            int p0 = nx*32;
            uint32_t stB = base0 + (uint32_t)(st*3*AVBUF*2);
            if (mode==0) {
                const __nv_bfloat16* gh = Ehb + (size_t)(rb+ar)*NN + p0 + apart*16;
                uint32_t sa = stB + (uint32_t)((ar*STA + apart*16)*2);
                cpa16(sa, gh); cpa16(sa+16, gh+8);
            } else {
                const __nv_bfloat16* gh = Ehb + (size_t)(p0+tr)*NN + rb + tcb;
                uint32_t sa = stB + (uint32_t)((tr*STT + tcb)*2);
                cpa16(sa, gh); cpa16(sa+16, gh+8);
            }
            {
                const __nv_bfloat16* gh = Vhb + (size_t)ar*NN + p0 + apart*16;
                const __nv_bfloat16* gl = Vlb + (size_t)ar*NN + p0 + apart*16;
                uint32_t sb = stB + (uint32_t)(AVBUF*2) + (uint32_t)((ar*STA + apart*16)*2);
                cpa16(sb, gh); cpa16(sb+16, gh+8);
                uint32_t sl = sb + (uint32_t)(AVBUF*2);
                cpa16(sl, gl); cpa16(sl+16, gl+8);
            }
            cp_commit();
        }
        if (it < 0) continue;
        if (nx < 64) cp_wait<1>(); else cp_wait<0>();
        __syncthreads();
        int st = it & 1;
        uint32_t stB = base0 + (uint32_t)(st*3*AVBUF*2);
        uint32_t aB  = stB;
        uint32_t bB  = stB + (uint32_t)(AVBUF*2);
        uint32_t blB = stB + (uint32_t)(2*AVBUF*2);
#pragma unroll
        for (int pass=0; pass<2; pass++) {
            uint32_t bBase = (pass==0) ? bB : blB;
#pragma unroll
            for (int ks=0; ks<2; ks++) {
                int kk = ks*16;
                uint32_t af[2][4], bf[4][4];
#pragma unroll
                for (int mi=0;mi<2;mi++) {
                    if (mode==0)
                        ldsm4 (af[mi], aB + (uint32_t)(((wr+mi*16+lrow)*STA + kk + lcol)*2));
                    else
                        ldsm4t(af[mi], aB + (uint32_t)(((kk+trow)*STT + wr + mi*16 + tcol)*2));
                }
#pragma unroll
                for (int nj=0;nj<4;nj++)
                    ldsm4(bf[nj], bBase + (uint32_t)(((wc+nj*16+lrow)*STA + kk + lcol)*2));
#pragma unroll
                for (int mi=0;mi<2;mi++)
#pragma unroll
                    for (int ni=0;ni<8;ni++) {
                        uint32_t bb[2] = { bf[ni>>1][ni&1], bf[ni>>1][(ni&1)+2] };
                        mma16816(acc[mi][ni], af[mi], bb);
                    }
            }
        }
        __syncthreads();
    }
    // epilogue: write A-role cat [hi|hi|lo]
    int g = lane>>2, tg = lane&3;
#pragma unroll
    for (int mi=0;mi<2;mi++)
#pragma unroll
        for (int ni=0;ni<8;ni++) {
            int r0 = wr + mi*16 + g, c = wc + ni*8 + 2*tg;
            __nv_bfloat162 hp, lp;
            split2(acc[mi][ni][0], acc[mi][ni][1], hp, lp);
            __nv_bfloat16* p = Ob + (size_t)r0*KCAT + c;
            *(__nv_bfloat162*)(p)     = hp;
            *(__nv_bfloat162*)(p+128) = hp;
            *(__nv_bfloat162*)(p+256) = lp;
            split2(acc[mi][ni][2], acc[mi][ni][3], hp, lp);
            p = Ob + (size_t)(r0+8)*KCAT + c;
            *(__nv_bfloat162*)(p)     = hp;
            *(__nv_bfloat162*)(p+128) = hp;
            *(__nv_bfloat162*)(p+256) = lp;
        }
}

// ---------------- launch ---------------------------------------------------
extern "C" void kernel_launch(void* const* d_in, const int* in_sizes, int n_in,
                              void* d_out, int out_size)
{
    const float* x1 = (const float*)d_in[0];
    const float* x2 = (const float*)d_in[1];
    const float* Wk = (const float*)d_in[2];
    const float* Wv = (const float*)d_in[3];
    const float* Wo = (const float*)d_in[4];
    const float* bo = (const float*)d_in[5];
    float* msg1 = (float*)d_out;
    float* msg2 = msg1 + (size_t)BB*NN*DD;

    __nv_bfloat16 *X1c,*X2c,*Wkc,*Wvc,*Woc,*H1c,*H2c,*Eh,*Vt1h,*Vt1l,*Vt2h,*Vt2l,*N12c,*N21c;
    float *V1,*V2,*rowp,*colp;
    cudaGetSymbolAddress((void**)&X1c, g_X1cat);
    cudaGetSymbolAddress((void**)&X2c, g_X2cat);
    cudaGetSymbolAddress((void**)&Wkc, g_Wkcat);
    cudaGetSymbolAddress((void**)&Wvc, g_Wvcat);
    cudaGetSymbolAddress((void**)&Woc, g_Wocat);
    cudaGetSymbolAddress((void**)&H1c, g_H1cat);
    cudaGetSymbolAddress((void**)&H2c, g_H2cat);
    cudaGetSymbolAddress((void**)&V1,  g_V1);
    cudaGetSymbolAddress((void**)&V2,  g_V2);
    cudaGetSymbolAddress((void**)&Eh,  g_Eh);
    cudaGetSymbolAddress((void**)&rowp,g_rowp);
    cudaGetSymbolAddress((void**)&colp,g_colp);
    cudaGetSymbolAddress((void**)&Vt1h,g_Vt1h);
    cudaGetSymbolAddress((void**)&Vt1l,g_Vt1l);
    cudaGetSymbolAddress((void**)&Vt2h,g_Vt2h);
    cudaGetSymbolAddress((void**)&Vt2l,g_Vt2l);
    cudaGetSymbolAddress((void**)&N12c,g_N12c);
    cudaGetSymbolAddress((void**)&N21c,g_N21c);

    const int AV_DYN = 2*3*AVBUF*2;            // 61440 B
    static bool attr_done = false;
    if (!attr_done) {
        cudaFuncSetAttribute(attn_av_bf16, cudaFuncAttributeMaxDynamicSharedMemorySize, AV_DYN);
        attr_done = true;
    }

    dim3 thr(256);

    // 0) split inputs/weights to cat layouts
    xcat<<<dim3(2048,1,2),thr>>>(x1, x2, X1c, X2c);
    wcat<<<dim3(16,1,3),thr>>>(Wk, Wv, Wo, Wkc, Wvc, Woc);

    // 1) K and V projections in ONE launch (z=4)
    mma_kv<<<dim3(128,1,4),thr>>>(X1c, X2c, Wkc, Wvc, H1c, H2c, V1, V2);

    // 2) E = bf16(exp(S - C)) + self-normalized stats
    gemm_s_exp<<<dim3(16,16,8),thr>>>(H1c, H2c, Eh, rowp, colp);

    // 3) V: fused Z-combine + scale + transpose + split
    vprep<<<dim3(64,1,16),thr>>>(V2, colp, V1, rowp, Vt2h, Vt2l, Vt1h, Vt1l);

    // 4) AV (writes N cat directly)
    attn_av_bf16<<<dim3(16,2,8),thr,AV_DYN>>>(Eh, Vt2h, Vt2l, Vt1h, Vt1l, N12c, N21c);

    // 5) output projection + bias + leaky relu
    mma_out<<<dim3(128,1,2),thr>>>(N12c, N21c, Woc, msg1, msg2, bo);
}